// round 2
// baseline (speedup 1.0000x reference)
#include <cuda_runtime.h>

#define NN 256
#define CH 20

// Duplicated effective kernels: per (p,k) 52 floats = {e0,e0,e1,e1,...,e24,e24,B,B}
__device__ __align__(16) float gEd[144 * 52];

// ---------------------------------------------------------------------------
// packed f32x2 helpers
// ---------------------------------------------------------------------------
__device__ __forceinline__ unsigned long long pk2(float lo, float hi) {
    unsigned long long r;
    asm("mov.b64 %0, {%1, %2};" : "=l"(r) : "f"(lo), "f"(hi));
    return r;
}
__device__ __forceinline__ void upk2(unsigned long long v, float& lo, float& hi) {
    asm("mov.b64 {%0, %1}, %2;" : "=f"(lo), "=f"(hi) : "l"(v));
}
__device__ __forceinline__ unsigned long long ff2(unsigned long long a,
                                                  unsigned long long b,
                                                  unsigned long long c) {
    unsigned long long d;
    asm("fma.rn.f32x2 %0, %1, %2, %3;" : "=l"(d) : "l"(a), "l"(b), "l"(c));
    return d;
}

// ---------------------------------------------------------------------------
// Kernel 1: compose W1 (1->20,3x3) with W2 (20->9,3x3) into effective 5x5 + bias.
// One warp per (p,k) pair; lanes = channels; shfl_xor reduction.
// ---------------------------------------------------------------------------
__global__ void k_precompute(const float* __restrict__ W1, const float* __restrict__ b1,
                             const float* __restrict__ W2, const float* __restrict__ b2) {
    int w = blockIdx.x * 4 + (threadIdx.x >> 5);
    int lane = threadIdx.x & 31;
    if (w >= 144) return;
    int p = w / 9, k = w % 9;

    float e[25];
#pragma unroll
    for (int i = 0; i < 25; i++) e[i] = 0.f;
    float bacc = 0.f;

    if (lane < CH) {
        int c = lane;
        float w1[9];
        const float* w1p = W1 + (p * CH + c) * 9;
#pragma unroll
        for (int a = 0; a < 9; a++) w1[a] = __ldg(w1p + a);
        const float* w2p = W2 + ((p * 9 + k) * CH + c) * 9;
        float s2 = 0.f;
#pragma unroll
        for (int bq = 0; bq < 9; bq++) {
            float w2 = __ldg(w2p + bq);
            s2 += w2;
            int by = bq / 3, bx = bq % 3;
#pragma unroll
            for (int a = 0; a < 9; a++) {
                int ay = a / 3, ax = a % 3;
                e[(ay + by) * 5 + (ax + bx)] += w1[a] * w2;
            }
        }
        bacc = s2 * __ldg(b1 + p * CH + c);
    }

#pragma unroll
    for (int o = 16; o > 0; o >>= 1) {
#pragma unroll
        for (int i = 0; i < 25; i++) e[i] += __shfl_xor_sync(0xFFFFFFFFu, e[i], o);
        bacc += __shfl_xor_sync(0xFFFFFFFFu, bacc, o);
    }

    if (lane == 0) {
        float* d = gEd + w * 52;
#pragma unroll
        for (int i = 0; i < 25; i++) { d[2 * i] = e[i]; d[2 * i + 1] = e[i]; }
        float B = __ldg(b2 + w) + bacc;
        d[50] = B; d[51] = B;
    }
}

// ---------------------------------------------------------------------------
// Kernel 2: main fused kernel, packed f32x2, 2 vertical pixels per thread.
// Tile 32 wide x 16 tall, 256 threads. Exact off the outermost image ring;
// ring pixels written 0 (k_border adds exact values).
// ---------------------------------------------------------------------------
__global__ void __launch_bounds__(256, 2) k_main(const float* __restrict__ img,
                                                 const float* __restrict__ x,
                                                 float* __restrict__ y) {
    __shared__ __align__(16) float sEd[144 * 52];   // 29952 B
    __shared__ float sImg[20 * 36];                 //  2880 B
    __shared__ float sX[4][18 * 34];                //  9792 B

    const int b  = blockIdx.z;
    const int n0 = blockIdx.y * 16;
    const int m0 = blockIdx.x * 32;
    const int t  = threadIdx.x;

    // stage E (float4 bulk copy)
    {
        const float4* src = reinterpret_cast<const float4*>(gEd);
        float4* dst = reinterpret_cast<float4*>(sEd);
        for (int i = t; i < 144 * 52 / 4; i += 256) dst[i] = src[i];
    }
    const float* imgb = img + b * NN * NN;
    for (int i = t; i < 20 * 36; i += 256) {
        int r = i / 36, c = i % 36;
        int gn = n0 + r - 2, gm = m0 + c - 2;
        float v = 0.f;
        if ((unsigned)gn < NN && (unsigned)gm < NN) v = __ldg(imgb + gn * NN + gm);
        sImg[i] = v;
    }
#pragma unroll
    for (int j = 0; j < 4; j++) {
        const float* xb = x + ((b * 4 + j) * NN) * NN;
        for (int i = t; i < 18 * 34; i += 256) {
            int r = i / 34, c = i % 34;
            int gn = n0 + r - 1, gm = m0 + c - 1;
            float v = 0.f;
            if ((unsigned)gn < NN && (unsigned)gm < NN) v = __ldg(xb + gn * NN + gm);
            sX[j][i] = v;
        }
    }
    __syncthreads();

    const int tx = t & 31;
    const int r0 = (t >> 5) * 2;    // two consecutive local rows per thread

    // packed image patch pairs: ipP[u*5+v] = {img(r0+u, tx+v), img(r0+1+u, tx+v)}
    unsigned long long ipP[25];
#pragma unroll
    for (int u = 0; u < 5; u++)
#pragma unroll
        for (int v = 0; v < 5; v++)
            ipP[u * 5 + v] = pk2(sImg[(r0 + u) * 36 + tx + v],
                                 sImg[(r0 + u + 1) * 36 + tx + v]);

    unsigned long long acc[4];
#pragma unroll
    for (int i = 0; i < 4; i++) acc[i] = pk2(0.f, 0.f);

#pragma unroll 1
    for (int j = 0; j < 4; j++) {
        const float* sxj = sX[j];
#pragma unroll 1
        for (int k = 0; k < 9; k++) {
            const int di = k / 3;
            const int dj = k - 3 * di;
            const float* xp = sxj + (r0 + di) * 34 + tx + dj;
            const unsigned long long xv = pk2(xp[0], xp[34]);
#pragma unroll
            for (int i = 0; i < 4; i++) {
                const ulonglong2* ev =
                    reinterpret_cast<const ulonglong2*>(sEd + ((i * 4 + j) * 9 + k) * 52);
                ulonglong2 tb = ev[12];                 // {e24 pair, B pair}
                unsigned long long kv = ff2(tb.x, ipP[24], tb.y);
#pragma unroll
                for (int q = 0; q < 12; q++) {
                    ulonglong2 tq = ev[q];
                    kv = ff2(tq.x, ipP[2 * q], kv);
                    kv = ff2(tq.y, ipP[2 * q + 1], kv);
                }
                acc[i] = ff2(kv, xv, acc[i]);
            }
        }
    }

    const int gm = m0 + tx;
    const int gnA = n0 + r0, gnB = gnA + 1;
    const bool mcol = (gm == 0) | (gm == NN - 1);
#pragma unroll
    for (int i = 0; i < 4; i++) {
        float lo, hi;
        upk2(acc[i], lo, hi);
        if (mcol) { lo = 0.f; hi = 0.f; }
        if (gnA == 0) lo = 0.f;
        if (gnB == NN - 1) hi = 0.f;
        float* yb = y + (((b * 4 + i) * NN) + gnA) * NN + gm;
        yb[0]  = lo;
        yb[NN] = hi;
    }
}

// ---------------------------------------------------------------------------
// Kernel 3: exact two-conv evaluation on the 1-pixel border ring.
// ---------------------------------------------------------------------------
__global__ void __launch_bounds__(256) k_border(const float* __restrict__ img,
                                                const float* __restrict__ x,
                                                const float* __restrict__ W1,
                                                const float* __restrict__ b1,
                                                const float* __restrict__ W2,
                                                const float* __restrict__ b2,
                                                float* __restrict__ y) {
    __shared__ float sW1[180];
    __shared__ float sb1[20];
    __shared__ float sW2[1620];
    __shared__ float sb2[9];

    const int p = blockIdx.x;
    const int t = threadIdx.x;
    for (int i = t; i < 180; i += 256) sW1[i] = W1[p * 180 + i];
    for (int i = t; i < 1620; i += 256) sW2[i] = W2[p * 1620 + i];
    if (t < 20) sb1[t] = b1[p * 20 + t];
    if (t < 9)  sb2[t] = b2[p * 9 + t];
    __syncthreads();

    int idx = blockIdx.y * 256 + t;
    if (idx >= 4080) return;                 // 4 batches x 1020 ring pixels
    int b = idx / 1020;
    int r = idx % 1020;
    int n, m;
    if (r < 256)       { n = 0;   m = r; }
    else if (r < 512)  { n = 255; m = r - 256; }
    else { int r2 = r - 512; n = 1 + (r2 >> 1); m = (r2 & 1) ? 255 : 0; }

    const float* imgb = img + b * NN * NN;
    float ipat[25];
#pragma unroll
    for (int u = 0; u < 5; u++)
#pragma unroll
        for (int v = 0; v < 5; v++) {
            int gn = n + u - 2, gm = m + v - 2;
            ipat[u * 5 + v] = ((unsigned)gn < NN && (unsigned)gm < NN)
                              ? __ldg(imgb + gn * NN + gm) : 0.f;
        }

    float hmask[9];
#pragma unroll
    for (int q = 0; q < 9; q++) {
        int qy = q / 3, qx = q % 3;
        int hn = n + qy - 1, hm = m + qx - 1;
        hmask[q] = ((unsigned)hn < NN && (unsigned)hm < NN) ? 1.f : 0.f;
    }

    float K[9];
#pragma unroll
    for (int k = 0; k < 9; k++) K[k] = sb2[k];

#pragma unroll 1
    for (int c = 0; c < CH; c++) {
        float h[9];
#pragma unroll
        for (int q = 0; q < 9; q++) {
            int qy = q / 3, qx = q % 3;
            float s = sb1[c];
#pragma unroll
            for (int a = 0; a < 9; a++) {
                int ay = a / 3, ax = a % 3;
                s += sW1[c * 9 + a] * ipat[(qy + ay) * 5 + (qx + ax)];
            }
            h[q] = s * hmask[q];
        }
#pragma unroll
        for (int k = 0; k < 9; k++)
#pragma unroll
            for (int q = 0; q < 9; q++)
                K[k] += sW2[(k * CH + c) * 9 + q] * h[q];
    }

    const int i = p >> 2, j = p & 3;
    const float* xb = x + ((b * 4 + j) * NN) * NN;
    float s = 0.f;
#pragma unroll
    for (int k = 0; k < 9; k++) {
        int di = k / 3, dj = k % 3;
        int gn = n + di - 1, gm = m + dj - 1;
        float xv = ((unsigned)gn < NN && (unsigned)gm < NN)
                   ? __ldg(xb + gn * NN + gm) : 0.f;
        s += K[k] * xv;
    }
    atomicAdd(&y[(((b * 4 + i) * NN) + n) * NN + m], s);
}

// ---------------------------------------------------------------------------
extern "C" void kernel_launch(void* const* d_in, const int* in_sizes, int n_in,
                              void* d_out, int out_size) {
    const float* image = (const float*)d_in[0];  // (4,256,256)
    const float* x     = (const float*)d_in[1];  // (4,4,256,256)
    const float* W1    = (const float*)d_in[2];  // (16,20,1,3,3)
    const float* b1    = (const float*)d_in[3];  // (16,20)
    const float* W2    = (const float*)d_in[4];  // (16,9,20,3,3)
    const float* b2    = (const float*)d_in[5];  // (16,9)
    float* y = (float*)d_out;                    // (4,4,256,256)

    k_precompute<<<36, 128>>>(W1, b1, W2, b2);   // one warp per (p,k)

    dim3 g2(NN / 32, NN / 16, 4);                // 8 x 16 x 4 = 512 blocks
    k_main<<<g2, 256>>>(image, x, y);

    dim3 g3(16, 16);                             // 16 p-values x 16 pixel chunks
    k_border<<<g3, 256>>>(image, x, W1, b1, W2, b2, y);
}

// round 4
// speedup vs baseline: 1.7613x; 1.7613x over previous
#include <cuda_runtime.h>
#include <cuda_bf16.h>
#include <cstdint>

#define NN 256
#define CH 20

// E/bias matrix, bf16 split, permuted column order:
//   n = (j*9+k9)*4 + i   where p = i*4+j  (i = out-ch, j = in-ch)
// plane 0 (hi): gEB[n*32 + k], plane 1 (lo): gEB[4608 + n*32 + k]
// k: 0..24 = E[5x5], 25 = bias, 26..31 = 0
__device__ __align__(16) __nv_bfloat16 gEB[2 * 144 * 32];

__device__ __forceinline__ uint32_t pkbf(__nv_bfloat16 a, __nv_bfloat16 b) {
    return (uint32_t)__bfloat16_as_ushort(a) | ((uint32_t)__bfloat16_as_ushort(b) << 16);
}

__device__ __forceinline__ void mma16816(float& d0, float& d1, float& d2, float& d3,
                                         uint32_t a0, uint32_t a1, uint32_t a2, uint32_t a3,
                                         uint32_t b0, uint32_t b1) {
    asm volatile(
        "mma.sync.aligned.m16n8k16.row.col.f32.bf16.bf16.f32 "
        "{%0,%1,%2,%3}, {%4,%5,%6,%7}, {%8,%9}, {%0,%1,%2,%3};"
        : "+f"(d0), "+f"(d1), "+f"(d2), "+f"(d3)
        : "r"(a0), "r"(a1), "r"(a2), "r"(a3), "r"(b0), "r"(b1));
}

// ---------------------------------------------------------------------------
// Kernel 1: compose W1 (1->20,3x3) with W2 (20->9,3x3) -> 5x5 E + bias,
// emit bf16 hi/lo planes in permuted-N layout. One warp per (p,k9).
// ---------------------------------------------------------------------------
__global__ void k_precompute(const float* __restrict__ W1, const float* __restrict__ b1,
                             const float* __restrict__ W2, const float* __restrict__ b2) {
    int w = blockIdx.x * 4 + (threadIdx.x >> 5);
    int lane = threadIdx.x & 31;
    if (w >= 144) return;
    int p = w / 9, k9 = w % 9;

    float e[25];
#pragma unroll
    for (int i = 0; i < 25; i++) e[i] = 0.f;
    float bacc = 0.f;

    if (lane < CH) {
        int c = lane;
        float w1[9];
        const float* w1p = W1 + (p * CH + c) * 9;
#pragma unroll
        for (int a = 0; a < 9; a++) w1[a] = __ldg(w1p + a);
        const float* w2p = W2 + ((p * 9 + k9) * CH + c) * 9;
        float s2 = 0.f;
#pragma unroll
        for (int bq = 0; bq < 9; bq++) {
            float w2v = __ldg(w2p + bq);
            s2 += w2v;
            int by = bq / 3, bx = bq % 3;
#pragma unroll
            for (int a = 0; a < 9; a++) {
                int ay = a / 3, ax = a % 3;
                e[(ay + by) * 5 + (ax + bx)] += w1[a] * w2v;
            }
        }
        bacc = s2 * __ldg(b1 + p * CH + c);
    }
#pragma unroll
    for (int o = 16; o > 0; o >>= 1) {
#pragma unroll
        for (int i = 0; i < 25; i++) e[i] += __shfl_xor_sync(0xFFFFFFFFu, e[i], o);
        bacc += __shfl_xor_sync(0xFFFFFFFFu, bacc, o);
    }

    if (lane == 0) {
        int i = p >> 2, j = p & 3;
        int n = (j * 9 + k9) * 4 + i;
        __nv_bfloat16* dh = gEB + n * 32;
        __nv_bfloat16* dl = gEB + 4608 + n * 32;
        __nv_bfloat16 z = __ushort_as_bfloat16(0);
        float B = __ldg(b2 + w) + bacc;
#pragma unroll
        for (int q = 0; q < 32; q++) {
            float v = (q < 25) ? e[q] : (q == 25 ? B : 0.f);
            __nv_bfloat16 h = __float2bfloat16(v);
            dh[q] = (q <= 25) ? h : z;
            dl[q] = (q <= 25) ? __float2bfloat16(v - __bfloat162float(h)) : z;
        }
    }
}

// off(jk): smem-x offset for combined (j,k9) index jk = j*9+k9
__device__ __forceinline__ constexpr int OFFJK(int jk) {
    return (jk / 9) * 180 + ((jk % 9) / 3) * 18 + ((jk % 9) % 3);
}

// ---------------------------------------------------------------------------
// Kernel 2: HMMA K-GEMM + fused contraction epilogue.
// CTA = 8x16 pixel tile; warp w = pixel row w (16 MMA rows = pixel columns).
// N=144 (18 n-steps), K=32 (2 k-steps), 3 split passes.
// ---------------------------------------------------------------------------
__global__ void __launch_bounds__(256, 2) k_main(const float* __restrict__ img,
                                                 const float* __restrict__ x,
                                                 float* __restrict__ y) {
    __shared__ float sImg[240];                   // 12 x 20
    __shared__ float sX[720];                     // 4 x 10 x 18
    __shared__ __align__(16) uint32_t sBh[144 * 20];
    __shared__ __align__(16) uint32_t sBl[144 * 20];

    const int t = threadIdx.x;
    const int w = t >> 5, lane = t & 31;
    const int g = lane >> 2, tg = lane & 3;
    const int b = blockIdx.z, TR = blockIdx.y * 8, TC = blockIdx.x * 16;

    const float* imgb = img + b * NN * NN;
    for (int i = t; i < 240; i += 256) {
        int rr = i / 20, cc = i % 20;
        int gn = TR + rr - 2, gm = TC + cc - 2;
        float v = 0.f;
        if ((unsigned)gn < NN && (unsigned)gm < NN) v = __ldg(imgb + gn * NN + gm);
        sImg[i] = v;
    }
#pragma unroll
    for (int j = 0; j < 4; j++) {
        const float* xb = x + (b * 4 + j) * NN * NN;
        for (int i = t; i < 180; i += 256) {
            int rr = i / 18, cc = i % 18;
            int gn = TR + rr - 1, gm = TC + cc - 1;
            float v = 0.f;
            if ((unsigned)gn < NN && (unsigned)gm < NN) v = __ldg(xb + gn * NN + gm);
            sX[j * 180 + i] = v;
        }
    }
    {   // stage B planes into smem, row stride 20 words (80 B, conflict-free)
        const uint4* src = reinterpret_cast<const uint4*>(gEB);
        for (int i = t; i < 576; i += 256) {
            int n = i >> 2, q = i & 3;
            uint4 vh = __ldg(src + i);
            uint4 vl = __ldg(src + 576 + i);
            *reinterpret_cast<uint4*>(&sBh[n * 20 + q * 4]) = vh;
            *reinterpret_cast<uint4*>(&sBl[n * 20 + q * 4]) = vl;
        }
    }
    __syncthreads();

    // --- build A fragments (pixel row = w, A-rows = pixel columns) ---
    const int pc0 = g, pc1 = g + 8;
    uint32_t ah[2][4], al[2][4];
    {
        auto pv = [&](int pc, int c) -> float {
            if (c == 25) return 1.f;
            if (c > 25) return 0.f;
            int u = c / 5, v = c - 5 * u;
            return sImg[(w + u) * 20 + pc + v];
        };
#pragma unroll
        for (int ks = 0; ks < 2; ks++) {
            const int base = ks * 16;
            const int cols[2] = {base + 2 * tg, base + 2 * tg + 8};
#pragma unroll
            for (int half = 0; half < 2; half++) {
                int c = cols[half];
                float f00 = pv(pc0, c),     f01 = pv(pc0, c + 1);
                float f10 = pv(pc1, c),     f11 = pv(pc1, c + 1);
                __nv_bfloat16 h00 = __float2bfloat16(f00), h01 = __float2bfloat16(f01);
                __nv_bfloat16 h10 = __float2bfloat16(f10), h11 = __float2bfloat16(f11);
                ah[ks][half * 2 + 0] = pkbf(h00, h01);        // row pc0 -> a0/a2
                ah[ks][half * 2 + 1] = pkbf(h10, h11);        // row pc1 -> a1/a3
                al[ks][half * 2 + 0] = pkbf(__float2bfloat16(f00 - __bfloat162float(h00)),
                                            __float2bfloat16(f01 - __bfloat162float(h01)));
                al[ks][half * 2 + 1] = pkbf(__float2bfloat16(f10 - __bfloat162float(h10)),
                                            __float2bfloat16(f11 - __bfloat162float(h11)));
            }
        }
    }

    float sa0 = 0.f, sb0 = 0.f, sa1 = 0.f, sb1 = 0.f;
    const int th = tg >> 1;
    const int xbase = w * 18;

#pragma unroll
    for (int ni = 0; ni < 18; ni++) {
        float d0 = 0.f, d1 = 0.f, d2 = 0.f, d3 = 0.f;
        const int nb = (ni * 8 + g) * 20 + tg;
#pragma unroll
        for (int ks = 0; ks < 2; ks++) {
            uint32_t bh0 = sBh[nb + ks * 8], bh1 = sBh[nb + 4 + ks * 8];
            uint32_t bl0 = sBl[nb + ks * 8], bl1 = sBl[nb + 4 + ks * 8];
            mma16816(d0, d1, d2, d3, ah[ks][0], ah[ks][1], ah[ks][2], ah[ks][3], bh0, bh1);
            mma16816(d0, d1, d2, d3, al[ks][0], al[ks][1], al[ks][2], al[ks][3], bh0, bh1);
            mma16816(d0, d1, d2, d3, ah[ks][0], ah[ks][1], ah[ks][2], ah[ks][3], bl0, bl1);
        }
        // contraction: cols ni*8+2tg (ch (2tg)&3) and +1 (ch +1); jk = 2ni + (tg>>1)
        const int offA = OFFJK(2 * ni);
        const int offB = OFFJK(2 * ni + 1);
        const int off = (th ? offB : offA) + xbase;
        float xv0 = sX[off + pc0];
        float xv1 = sX[off + pc1];
        sa0 = fmaf(d0, xv0, sa0);
        sb0 = fmaf(d1, xv0, sb0);
        sa1 = fmaf(d2, xv1, sa1);
        sb1 = fmaf(d3, xv1, sb1);
    }

    // reduce over the two lanes holding the same channel set (tg ^ 2)
    sa0 += __shfl_xor_sync(0xFFFFFFFFu, sa0, 2);
    sb0 += __shfl_xor_sync(0xFFFFFFFFu, sb0, 2);
    sa1 += __shfl_xor_sync(0xFFFFFFFFu, sa1, 2);
    sb1 += __shfl_xor_sync(0xFFFFFFFFu, sb1, 2);

    if (tg < 2) {
        const int ch0 = tg * 2;              // tg=0 -> ch 0,1 ; tg=1 -> ch 2,3
        const int gr = TR + w;
        const int gc0 = TC + pc0, gc1 = TC + pc1;
        const bool rr = (gr == 0) | (gr == NN - 1);
        const bool r0 = rr | (gc0 == 0) | (gc0 == NN - 1);
        const bool r1 = rr | (gc1 == 0) | (gc1 == NN - 1);
        float* y0 = y + ((b * 4 + ch0) * NN + gr) * NN;
        float* y1 = y + ((b * 4 + ch0 + 1) * NN + gr) * NN;
        y0[gc0] = r0 ? 0.f : sa0;
        y1[gc0] = r0 ? 0.f : sb0;
        y0[gc1] = r1 ? 0.f : sa1;
        y1[gc1] = r1 ? 0.f : sb1;
    }
}

// ---------------------------------------------------------------------------
// Kernel 3: exact two-conv evaluation on the 1-pixel border ring.
// ---------------------------------------------------------------------------
__global__ void __launch_bounds__(256) k_border(const float* __restrict__ img,
                                                const float* __restrict__ x,
                                                const float* __restrict__ W1,
                                                const float* __restrict__ b1,
                                                const float* __restrict__ W2,
                                                const float* __restrict__ b2,
                                                float* __restrict__ y) {
    __shared__ float sW1[180];
    __shared__ float sb1[20];
    __shared__ float sW2[1620];
    __shared__ float sb2[9];

    const int p = blockIdx.x;
    const int t = threadIdx.x;
    for (int i = t; i < 180; i += 256) sW1[i] = W1[p * 180 + i];
    for (int i = t; i < 1620; i += 256) sW2[i] = W2[p * 1620 + i];
    if (t < 20) sb1[t] = b1[p * 20 + t];
    if (t < 9)  sb2[t] = b2[p * 9 + t];
    __syncthreads();

    int idx = blockIdx.y * 256 + t;
    if (idx >= 4080) return;
    int b = idx / 1020;
    int r = idx % 1020;
    int n, m;
    if (r < 256)       { n = 0;   m = r; }
    else if (r < 512)  { n = 255; m = r - 256; }
    else { int r2 = r - 512; n = 1 + (r2 >> 1); m = (r2 & 1) ? 255 : 0; }

    const float* imgb = img + b * NN * NN;
    float ipat[25];
#pragma unroll
    for (int u = 0; u < 5; u++)
#pragma unroll
        for (int v = 0; v < 5; v++) {
            int gn = n + u - 2, gm = m + v - 2;
            ipat[u * 5 + v] = ((unsigned)gn < NN && (unsigned)gm < NN)
                              ? __ldg(imgb + gn * NN + gm) : 0.f;
        }

    float hmask[9];
#pragma unroll
    for (int q = 0; q < 9; q++) {
        int qy = q / 3, qx = q % 3;
        int hn = n + qy - 1, hm = m + qx - 1;
        hmask[q] = ((unsigned)hn < NN && (unsigned)hm < NN) ? 1.f : 0.f;
    }

    float K[9];
#pragma unroll
    for (int k = 0; k < 9; k++) K[k] = sb2[k];

#pragma unroll 1
    for (int c = 0; c < CH; c++) {
        float h[9];
#pragma unroll
        for (int q = 0; q < 9; q++) {
            int qy = q / 3, qx = q % 3;
            float s = sb1[c];
#pragma unroll
            for (int a = 0; a < 9; a++) {
                int ay = a / 3, ax = a % 3;
                s += sW1[c * 9 + a] * ipat[(qy + ay) * 5 + (qx + ax)];
            }
            h[q] = s * hmask[q];
        }
#pragma unroll
        for (int k = 0; k < 9; k++)
#pragma unroll
            for (int q = 0; q < 9; q++)
                K[k] += sW2[(k * CH + c) * 9 + q] * h[q];
    }

    const int i = p >> 2, j = p & 3;
    const float* xb = x + (b * 4 + j) * NN * NN;
    float s = 0.f;
#pragma unroll
    for (int k = 0; k < 9; k++) {
        int di = k / 3, dj = k % 3;
        int gn = n + di - 1, gm = m + dj - 1;
        float xv = ((unsigned)gn < NN && (unsigned)gm < NN)
                   ? __ldg(xb + gn * NN + gm) : 0.f;
        s += K[k] * xv;
    }
    atomicAdd(&y[((b * 4 + i) * NN + n) * NN + m], s);
}

// ---------------------------------------------------------------------------
extern "C" void kernel_launch(void* const* d_in, const int* in_sizes, int n_in,
                              void* d_out, int out_size) {
    const float* image = (const float*)d_in[0];
    const float* x     = (const float*)d_in[1];
    const float* W1    = (const float*)d_in[2];
    const float* b1    = (const float*)d_in[3];
    const float* W2    = (const float*)d_in[4];
    const float* b2    = (const float*)d_in[5];
    float* y = (float*)d_out;

    k_precompute<<<36, 128>>>(W1, b1, W2, b2);

    dim3 g2(16, 32, 4);                          // 2048 CTAs
    k_main<<<g2, 256>>>(image, x, y);

    dim3 g3(16, 16);
    k_border<<<g3, 256>>>(image, x, W1, b1, W2, b2, y);
}